// round 1
// baseline (speedup 1.0000x reference)
#include <cuda_runtime.h>
#include <cstddef>

// out[b,c,a,j] = mean_{4x4}( images[b,c, 4*sr .. 4*sr+3, 4*sc .. 4*sc+3] )
//   sr = (a - W_shifts[b]) mod 56,  sc = (j - H_shifts[b]) mod 56
// (reference passes W_shifts as the row shift dy, H_shifts as the col shift dx)

#define H_IN 224
#define W_IN 224
#define H_OUT 56
#define W_OUT 56
#define CH 3

__global__ void __launch_bounds__(224)
downsample_wrap_translate_kernel(const float4* __restrict__ img,
                                 const int* __restrict__ h_shifts,
                                 const int* __restrict__ w_shifts,
                                 float* __restrict__ out)
{
    // block (56,4); grid (14, B*C)
    const int j  = threadIdx.x;                       // output col 0..55
    const int a  = blockIdx.x * 4 + threadIdx.y;      // output row 0..55
    const int bc = blockIdx.y;                        // b*3 + c
    const int b  = bc / CH;

    const int dx = h_shifts[b];   // column shift
    const int dy = w_shifts[b];   // row shift

    int sr = a - dy; if (sr < 0) sr += H_OUT;
    int sc = j - dx; if (sc < 0) sc += W_OUT;

    // input plane: 224x224 floats = 224 rows of 56 float4
    const float4* p = img + (size_t)bc * (H_IN * W_IN / 4)
                          + (size_t)(sr * 4) * (W_IN / 4) + sc;

    const float4 v0 = p[0 * (W_IN / 4)];
    const float4 v1 = p[1 * (W_IN / 4)];
    const float4 v2 = p[2 * (W_IN / 4)];
    const float4 v3 = p[3 * (W_IN / 4)];

    float s = (v0.x + v0.y) + (v0.z + v0.w)
            + (v1.x + v1.y) + (v1.z + v1.w)
            + (v2.x + v2.y) + (v2.z + v2.w)
            + (v3.x + v3.y) + (v3.z + v3.w);

    out[(size_t)bc * (H_OUT * W_OUT) + a * W_OUT + j] = s * (1.0f / 16.0f);
}

extern "C" void kernel_launch(void* const* d_in, const int* in_sizes, int n_in,
                              void* d_out, int out_size)
{
    const float4* img = (const float4*)d_in[0];        // images (B,3,224,224) f32
    const int* h_shifts = (const int*)d_in[1];         // H_shifts (B,) i32 -> col shift
    const int* w_shifts = (const int*)d_in[2];         // W_shifts (B,) i32 -> row shift
    float* out = (float*)d_out;

    const int B = in_sizes[1];                         // 128
    dim3 block(W_OUT, 4);                              // 224 threads
    dim3 grid(H_OUT / 4, B * CH);                      // (14, 384)
    downsample_wrap_translate_kernel<<<grid, block>>>(img, h_shifts, w_shifts, out);
}